// round 14
// baseline (speedup 1.0000x reference)
#include <cuda_runtime.h>
#include <cuda_fp16.h>
#include <cstdint>

#define M_TOTAL 12608   // 64*197
#define K_DIM   768
#define R_DIM   192
#define BM      64
#define BN      192
#define BK      64
#define NCHUNK  12
#define A_BYTES (BM * 128)            // 8192
#define B_BYTES (BN * 128)            // 24576
#define STAGE   (A_BYTES + B_BYTES)   // 32768
#define NSTAGE  3
#define SMEM_DYN (NSTAGE * STAGE + 1024)   // 99328 -> 2 CTA/SM

#define M_TILES   197
#define A_MTILES  99                  // prep converts m_tiles 0..98 (rows 0..6335)
#define A_ROWS    (A_MTILES * BM)     // 6336
#define NCVT_CTAS 49                  // converter blocks: 49 * 128 rows = 6272 = rest of X
#define FLAG_TGT  6272u               // 49 CTAs * 128 threads

#define SWZ(o) ((o) ^ (((o) >> 3) & 0x70))

// allocation-free __device__ scratch
__device__ __half   g_Xh[(size_t)M_TOTAL * K_DIM];     // [M,K] fp16
__device__ __half   g_Wh[(size_t)3 * R_DIM * K_DIM];   // [3][N][K] K-major fp16
__device__ unsigned g_cnt;                             // converter completion counter

// ---------------- PTX helpers ----------------
__device__ __forceinline__ uint32_t smem_u32(const void* p) {
    uint32_t a;
    asm("{ .reg .u64 t; cvta.to.shared.u64 t, %1; cvt.u32.u64 %0, t; }" : "=r"(a) : "l"(p));
    return a;
}
__device__ __forceinline__ void cp16(uint32_t dst, const void* src) {
    asm volatile("cp.async.cg.shared.global [%0], [%1], 16;" :: "r"(dst), "l"(src) : "memory");
}
#define CP_COMMIT() asm volatile("cp.async.commit_group;" ::: "memory")
#define CP_WAIT0()  asm volatile("cp.async.wait_group 0;" ::: "memory")
#define CP_WAIT1()  asm volatile("cp.async.wait_group 1;" ::: "memory")

__device__ __forceinline__ void ldsm4(uint32_t* r, uint32_t addr) {
    asm volatile("ldmatrix.sync.aligned.m8n8.x4.shared.b16 {%0,%1,%2,%3}, [%4];"
                 : "=r"(r[0]), "=r"(r[1]), "=r"(r[2]), "=r"(r[3]) : "r"(addr));
}
__device__ __forceinline__ void mma16816(float* c, const uint32_t* a, const uint32_t* b) {
    asm volatile(
        "mma.sync.aligned.m16n8k16.row.col.f32.f16.f16.f32 "
        "{%0,%1,%2,%3}, {%4,%5,%6,%7}, {%8,%9}, {%0,%1,%2,%3};"
        : "+f"(c[0]), "+f"(c[1]), "+f"(c[2]), "+f"(c[3])
        : "r"(a[0]), "r"(a[1]), "r"(a[2]), "r"(a[3]), "r"(b[0]), "r"(b[1]));
}
__device__ __forceinline__ void flag_release_add1(unsigned* p) {
    asm volatile("red.release.gpu.global.add.u32 [%0], %1;" :: "l"(p), "r"(1u) : "memory");
}
__device__ __forceinline__ void spin_flag(const unsigned* p) {
    unsigned v;
    do {
        asm volatile("ld.acquire.gpu.global.u32 %0, [%1];" : "=r"(v) : "l"(p) : "memory");
        if (v >= FLAG_TGT) return;
        __nanosleep(128);
    } while (true);
}
__device__ __forceinline__ float gelu_exact(float x) {
    return 0.5f * x * (1.0f + erff(x * 0.70710678118654752f));
}

// ---------------- prep: part-A X + W transpose + counter reset ----------------
#define XA_BLK 594    // 6336 rows * 96 uint4 / (4*256)
#define W_BLK  432    // 3 * 24 * 6 tiles of 32x32
__global__ __launch_bounds__(256, 4)
void prep_kernel(const float4* __restrict__ X,
                 const float* __restrict__ Wq, const float* __restrict__ Wk,
                 const float* __restrict__ Wv) {
    __shared__ float s[32][33];

    if (blockIdx.x == 0 && threadIdx.x == 0) g_cnt = 0;   // reset every replay

    if (blockIdx.x < XA_BLK) {
        uint4* xh = reinterpret_cast<uint4*>(g_Xh);
        const int t = blockIdx.x * 256 + threadIdx.x;
        const int stride = XA_BLK * 256;
        float4 v[8];
        #pragma unroll
        for (int u = 0; u < 4; ++u) {
            int i = t + u * stride;                    // < 608256 always
            v[2 * u + 0] = __ldcs(&X[2 * i + 0]);
            v[2 * u + 1] = __ldcs(&X[2 * i + 1]);
        }
        #pragma unroll
        for (int u = 0; u < 4; ++u) {
            int i = t + u * stride;
            __half2 h0 = __floats2half2_rn(v[2*u].x,   v[2*u].y);
            __half2 h1 = __floats2half2_rn(v[2*u].z,   v[2*u].w);
            __half2 h2 = __floats2half2_rn(v[2*u+1].x, v[2*u+1].y);
            __half2 h3 = __floats2half2_rn(v[2*u+1].z, v[2*u+1].w);
            uint4 o;
            o.x = *reinterpret_cast<uint32_t*>(&h0);
            o.y = *reinterpret_cast<uint32_t*>(&h1);
            o.z = *reinterpret_cast<uint32_t*>(&h2);
            o.w = *reinterpret_cast<uint32_t*>(&h3);
            xh[i] = o;
        }
    } else {
        // W transpose: [K,N] fp32 -> [N,K] fp16 via padded 32x32 smem tiles
        const int bid2 = blockIdx.x - XA_BLK;      // 0..431
        const int w    = bid2 / 144;
        const int t2   = bid2 - w * 144;
        const int kt   = t2 / 6;
        const int nt   = t2 - kt * 6;
        const int k0   = kt * 32;
        const int n0   = nt * 32;
        const int tx   = threadIdx.x & 31;
        const int ty   = threadIdx.x >> 5;
        const float* W = (w == 0) ? Wq : (w == 1) ? Wk : Wv;

        #pragma unroll
        for (int r = 0; r < 4; ++r)
            s[ty + 8 * r][tx] = W[(size_t)(k0 + ty + 8 * r) * R_DIM + n0 + tx];
        __syncthreads();
        __half* out = g_Wh + (size_t)w * R_DIM * K_DIM;
        #pragma unroll
        for (int r = 0; r < 4; ++r)
            out[(size_t)(n0 + ty + 8 * r) * K_DIM + k0 + tx] =
                __float2half_rn(s[tx][ty + 8 * r]);
    }
}

// ---------------- chunk loader ----------------
__device__ __forceinline__ void load_chunk(int c, uint32_t st, const __half* Asrc,
                                           const __half* Bsrc, int tid) {
    #pragma unroll
    for (int u = 0; u < 4; ++u) {
        int idx = tid + u * 128;
        int row = idx >> 3;
        int j   = idx & 7;
        cp16(st + SWZ(row * 128 + j * 16),
             Asrc + (size_t)row * K_DIM + c * BK + j * 8);
    }
    #pragma unroll
    for (int u = 0; u < 12; ++u) {
        int idx = tid + u * 128;
        int row = idx >> 3;
        int j   = idx & 7;
        cp16(st + A_BYTES + SWZ(row * 128 + j * 16),
             Bsrc + (size_t)row * K_DIM + c * BK + j * 8);
    }
}

// ---------------- main: converter blocks (0..48) + GEMM tiles (49..639) ----------------
__global__ __launch_bounds__(128, 2)
void qkv_mma_kernel(const float* __restrict__ X, float* __restrict__ Out) {
    extern __shared__ char dynsm[];
    const int tid  = threadIdx.x;
    const int wid  = tid >> 5;
    const int lane = tid & 31;

    // ======== converter blocks: convert part-B X rows, then exit ========
    if (blockIdx.x < NCVT_CTAS) {
        const int c = blockIdx.x;
        const float4* src = reinterpret_cast<const float4*>(X)
                          + (size_t)(A_ROWS + c * 128) * 192;
        uint4* dst = reinterpret_cast<uint4*>(g_Xh)
                   + (size_t)(A_ROWS + c * 128) * 96;
        // 128 rows * 96 uint4 = 12288 outs; 96 per thread; batches of 8 for MLP
        #pragma unroll 1
        for (int b = 0; b < 12; ++b) {
            float4 v[16];
            #pragma unroll
            for (int u = 0; u < 8; ++u) {
                int i = (b * 8 + u) * 128 + tid;
                v[2 * u + 0] = __ldcs(&src[2 * i + 0]);
                v[2 * u + 1] = __ldcs(&src[2 * i + 1]);
            }
            #pragma unroll
            for (int u = 0; u < 8; ++u) {
                int i = (b * 8 + u) * 128 + tid;
                __half2 h0 = __floats2half2_rn(v[2*u].x,   v[2*u].y);
                __half2 h1 = __floats2half2_rn(v[2*u].z,   v[2*u].w);
                __half2 h2 = __floats2half2_rn(v[2*u+1].x, v[2*u+1].y);
                __half2 h3 = __floats2half2_rn(v[2*u+1].z, v[2*u+1].w);
                uint4 o;
                o.x = *reinterpret_cast<uint32_t*>(&h0);
                o.y = *reinterpret_cast<uint32_t*>(&h1);
                o.z = *reinterpret_cast<uint32_t*>(&h2);
                o.w = *reinterpret_cast<uint32_t*>(&h3);
                dst[i] = o;
            }
        }
        flag_release_add1(&g_cnt);    // release orders this thread's own stores
        return;
    }

    // ======== GEMM tiles ========
    const int g      = blockIdx.x - NCVT_CTAS;   // 0..590, m-major
    const int m_tile = g / 3;
    const int nb     = g - m_tile * 3;
    const int bm     = m_tile * BM;
    const int warp_n = wid * 48;

    if (m_tile >= A_MTILES) {        // rows converted by converter blocks
        if (tid == 0) spin_flag(&g_cnt);
        __syncthreads();
    }

    uint32_t base = (smem_u32(dynsm) + 1023u) & ~1023u;

    const __half* Asrc = g_Xh + (size_t)bm * K_DIM;
    const __half* Bsrc = g_Wh + (size_t)nb * R_DIM * K_DIM;

    const int a_row_off = lane & 15;
    const int a_k_off   = (lane >> 4) * 16;
    const int b_n_off   = (lane & 7) | ((lane & 16) >> 1);
    const int b_k_off   = (lane & 8) ? 16 : 0;

    float acc[4][6][4];
    #pragma unroll
    for (int i = 0; i < 4; ++i)
        #pragma unroll
        for (int j = 0; j < 6; ++j)
            #pragma unroll
            for (int q = 0; q < 4; ++q) acc[i][j][q] = 0.0f;

    load_chunk(0, base, Asrc, Bsrc, tid);          CP_COMMIT();
    load_chunk(1, base + STAGE, Asrc, Bsrc, tid);  CP_COMMIT();

    for (int j = 0; j < NCHUNK; ++j) {
        if (j + 1 < NCHUNK) { CP_WAIT1(); } else { CP_WAIT0(); }
        __syncthreads();

        if (j + 2 < NCHUNK) {
            load_chunk(j + 2, base + ((j + 2) % NSTAGE) * STAGE, Asrc, Bsrc, tid);
            CP_COMMIT();
        }

        const uint32_t a_sm = base + (j % NSTAGE) * STAGE;
        const uint32_t b_sm = a_sm + A_BYTES;

        #pragma unroll
        for (int ks = 0; ks < 4; ++ks) {
            uint32_t afrag[4][4], bfrag[3][4];
            #pragma unroll
            for (int mf = 0; mf < 4; ++mf)
                ldsm4(afrag[mf],
                      a_sm + SWZ((mf * 16 + a_row_off) * 128 + ks * 32 + a_k_off));
            #pragma unroll
            for (int nf2 = 0; nf2 < 3; ++nf2)
                ldsm4(bfrag[nf2],
                      b_sm + SWZ((warp_n + nf2 * 16 + b_n_off) * 128 + ks * 32 + b_k_off));
            #pragma unroll
            for (int mf = 0; mf < 4; ++mf)
                #pragma unroll
                for (int nf = 0; nf < 6; ++nf)
                    mma16816(acc[mf][nf], afrag[mf], &bfrag[nf >> 1][(nf & 1) * 2]);
        }
    }

    // ---- epilogue: GELU + float2 stores ----
    float* __restrict__ outbase =
        Out + (size_t)nb * (size_t)M_TOTAL * R_DIM + warp_n;
    const int rbase = bm + (lane >> 2);
    const int cbase = (lane & 3) * 2;
    #pragma unroll
    for (int mf = 0; mf < 4; ++mf) {
        #pragma unroll
        for (int half = 0; half < 2; ++half) {
            int row = rbase + mf * 16 + half * 8;
            float* op = outbase + (size_t)row * R_DIM + cbase;
            #pragma unroll
            for (int nf = 0; nf < 6; ++nf) {
                float2 o;
                o.x = gelu_exact(acc[mf][nf][half * 2 + 0]);
                o.y = gelu_exact(acc[mf][nf][half * 2 + 1]);
                *reinterpret_cast<float2*>(op + nf * 8) = o;
            }
        }
    }
}

extern "C" void kernel_launch(void* const* d_in, const int* in_sizes, int n_in,
                              void* d_out, int out_size) {
    const float* X  = (const float*)d_in[0];  // [64,197,768]
    const float* Wq = (const float*)d_in[1];  // [768,192]
    const float* Wk = (const float*)d_in[2];
    const float* Wv = (const float*)d_in[3];
    float* Out = (float*)d_out;

    cudaFuncSetAttribute(qkv_mma_kernel, cudaFuncAttributeMaxDynamicSharedMemorySize, SMEM_DYN);

    prep_kernel<<<XA_BLK + W_BLK, 256>>>((const float4*)X, Wq, Wk, Wv);

    qkv_mma_kernel<<<NCVT_CTAS + 591, 128, SMEM_DYN>>>(X, Out);
}

// round 15
// speedup vs baseline: 1.1364x; 1.1364x over previous
#include <cuda_runtime.h>
#include <cuda_fp16.h>
#include <cstdint>

#define M_TOTAL 12608   // 64*197 (divisible by 64 -> no M guards)
#define K_DIM   768
#define R_DIM   192
#define BM      64
#define BN      192
#define BK      64      // fp16 elems per chunk = 128B row
#define NCHUNK  12
#define A_BYTES (BM * 128)            // 8192
#define B_BYTES (BN * 128)            // 24576
#define STAGE   (A_BYTES + B_BYTES)   // 32768
#define NSTAGE  3
#define SMEM_DYN (NSTAGE * STAGE + 1024)   // 99328 -> 2 CTA/SM

#define SWZ(o) ((o) ^ (((o) >> 3) & 0x70))

// fp16 scratch (allocation-free __device__ globals)
__device__ __half g_Xh[(size_t)M_TOTAL * K_DIM];     // [M,K] row-major
__device__ __half g_Wh[(size_t)3 * R_DIM * K_DIM];   // [3][N=192][K=768] K-major

// ---------------- PTX helpers ----------------
__device__ __forceinline__ uint32_t smem_u32(const void* p) {
    uint32_t a;
    asm("{ .reg .u64 t; cvta.to.shared.u64 t, %1; cvt.u32.u64 %0, t; }" : "=r"(a) : "l"(p));
    return a;
}
__device__ __forceinline__ void cp16(uint32_t dst, const void* src) {
    asm volatile("cp.async.cg.shared.global [%0], [%1], 16;" :: "r"(dst), "l"(src) : "memory");
}
#define CP_COMMIT() asm volatile("cp.async.commit_group;" ::: "memory")
#define CP_WAIT0()  asm volatile("cp.async.wait_group 0;" ::: "memory")
#define CP_WAIT1()  asm volatile("cp.async.wait_group 1;" ::: "memory")

__device__ __forceinline__ void ldsm4(uint32_t* r, uint32_t addr) {
    asm volatile("ldmatrix.sync.aligned.m8n8.x4.shared.b16 {%0,%1,%2,%3}, [%4];"
                 : "=r"(r[0]), "=r"(r[1]), "=r"(r[2]), "=r"(r[3]) : "r"(addr));
}
__device__ __forceinline__ void mma16816(float* c, const uint32_t* a, const uint32_t* b) {
    asm volatile(
        "mma.sync.aligned.m16n8k16.row.col.f32.f16.f16.f32 "
        "{%0,%1,%2,%3}, {%4,%5,%6,%7}, {%8,%9}, {%0,%1,%2,%3};"
        : "+f"(c[0]), "+f"(c[1]), "+f"(c[2]), "+f"(c[3])
        : "r"(a[0]), "r"(a[1]), "r"(a[2]), "r"(a[3]), "r"(b[0]), "r"(b[1]));
}
__device__ __forceinline__ float gelu_exact(float x) {
    return 0.5f * x * (1.0f + erff(x * 0.70710678118654752f));
}

// ---------------- fused convert prepass (X stream + W smem-tile transpose) ----------------
#define XBLK 1182   // (12608*768/8 uint4) / (4*256)
#define WBLK 432    // 3 matrices * (768/32)*(192/32) tiles
__global__ __launch_bounds__(256, 4)
void cvt_xw_kernel(const float4* __restrict__ X,
                   const float* __restrict__ Wq, const float* __restrict__ Wk,
                   const float* __restrict__ Wv, uint4* __restrict__ xh_out) {
    __shared__ float s[32][33];      // padded transpose tile (W branch only)

    if (blockIdx.x < XBLK) {
        const int n_u4 = (M_TOTAL * K_DIM) / 8;              // 1210368
        const int t = blockIdx.x * blockDim.x + threadIdx.x;
        const int stride = XBLK * 256;
        float4 v[8];
        #pragma unroll
        for (int u = 0; u < 4; ++u) {
            int i = t + u * stride;
            if (i < n_u4) {
                v[2 * u + 0] = __ldcs(&X[2 * i + 0]);   // X is single-use: stream it
                v[2 * u + 1] = __ldcs(&X[2 * i + 1]);
            }
        }
        #pragma unroll
        for (int u = 0; u < 4; ++u) {
            int i = t + u * stride;
            if (i < n_u4) {
                __half2 h0 = __floats2half2_rn(v[2*u].x,   v[2*u].y);
                __half2 h1 = __floats2half2_rn(v[2*u].z,   v[2*u].w);
                __half2 h2 = __floats2half2_rn(v[2*u+1].x, v[2*u+1].y);
                __half2 h3 = __floats2half2_rn(v[2*u+1].z, v[2*u+1].w);
                uint4 o;
                o.x = *reinterpret_cast<uint32_t*>(&h0);
                o.y = *reinterpret_cast<uint32_t*>(&h1);
                o.z = *reinterpret_cast<uint32_t*>(&h2);
                o.w = *reinterpret_cast<uint32_t*>(&h3);
                xh_out[i] = o;       // g_Xh is re-read by GEMM: default (L2) hint
            }
        }
    } else {
        // W transpose: [K=768, N=192] fp32 -> [N, K] fp16, 32x32 smem tiles.
        const int bid2 = blockIdx.x - XBLK;      // 0..431
        const int w    = bid2 / 144;             // matrix 0..2
        const int t2   = bid2 - w * 144;
        const int kt   = t2 / 6;                 // 0..23
        const int nt   = t2 - kt * 6;            // 0..5
        const int k0   = kt * 32;
        const int n0   = nt * 32;
        const int tx   = threadIdx.x & 31;
        const int ty   = threadIdx.x >> 5;       // 0..7
        const float* W = (w == 0) ? Wq : (w == 1) ? Wk : Wv;

        // coalesced reads: 32 consecutive n per row
        #pragma unroll
        for (int r = 0; r < 4; ++r)
            s[ty + 8 * r][tx] = W[(size_t)(k0 + ty + 8 * r) * R_DIM + n0 + tx];
        __syncthreads();
        // contiguous fp16 writes: 32 consecutive k per n-row
        __half* out = g_Wh + (size_t)w * R_DIM * K_DIM;
        #pragma unroll
        for (int r = 0; r < 4; ++r)
            out[(size_t)(n0 + ty + 8 * r) * K_DIM + k0 + tx] =
                __float2half_rn(s[tx][ty + 8 * r]);
    }
}

// ---------------- chunk loader (cp.async, swizzled 128B rows) ----------------
__device__ __forceinline__ void load_chunk(int c, uint32_t st, const __half* Asrc,
                                           const __half* Bsrc, int tid) {
    // A: 64 rows x 8 16B-chunks = 512 -> 4 per thread (128 threads)
    #pragma unroll
    for (int u = 0; u < 4; ++u) {
        int idx = tid + u * 128;
        int row = idx >> 3;
        int j   = idx & 7;
        cp16(st + SWZ(row * 128 + j * 16),
             Asrc + (size_t)row * K_DIM + c * BK + j * 8);
    }
    // B: 192 rows x 8 = 1536 -> 12 per thread
    #pragma unroll
    for (int u = 0; u < 12; ++u) {
        int idx = tid + u * 128;
        int row = idx >> 3;
        int j   = idx & 7;
        cp16(st + A_BYTES + SWZ(row * 128 + j * 16),
             Bsrc + (size_t)row * K_DIM + c * BK + j * 8);
    }
}

// ---------------- GEMM: CTA 64x192, 4 warps (1x4), 3-stage, plain inner loop ----------------
__global__ __launch_bounds__(128, 2)
void qkv_mma_kernel(float* __restrict__ Out) {
    extern __shared__ char dynsm[];
    const int tid  = threadIdx.x;
    const int wid  = tid >> 5;                // 0..3
    const int lane = tid & 31;
    const int nb   = blockIdx.x;              // 0..2 -> q/k/v
    const int bm   = blockIdx.y * BM;

    const int warp_n = wid * 48;

    uint32_t base = (smem_u32(dynsm) + 1023u) & ~1023u;

    const __half* Asrc = g_Xh + (size_t)bm * K_DIM;
    const __half* Bsrc = g_Wh + (size_t)nb * R_DIM * K_DIM;

    // per-lane ldmatrix offsets
    const int a_row_off = lane & 15;
    const int a_k_off   = (lane >> 4) * 16;
    const int b_n_off   = (lane & 7) | ((lane & 16) >> 1);
    const int b_k_off   = (lane & 8) ? 16 : 0;

    float acc[4][6][4];
    #pragma unroll
    for (int i = 0; i < 4; ++i)
        #pragma unroll
        for (int j = 0; j < 6; ++j)
            #pragma unroll
            for (int q = 0; q < 4; ++q) acc[i][j][q] = 0.0f;

    // prologue: chunks 0,1 in flight (3-stage ring)
    load_chunk(0, base, Asrc, Bsrc, tid);          CP_COMMIT();
    load_chunk(1, base + STAGE, Asrc, Bsrc, tid);  CP_COMMIT();

    for (int j = 0; j < NCHUNK; ++j) {
        if (j + 1 < NCHUNK) { CP_WAIT1(); } else { CP_WAIT0(); }
        __syncthreads();                 // chunk j resident; stage (j+2)%3 free

        if (j + 2 < NCHUNK) {
            load_chunk(j + 2, base + ((j + 2) % NSTAGE) * STAGE, Asrc, Bsrc, tid);
            CP_COMMIT();
        }

        const uint32_t a_sm = base + (j % NSTAGE) * STAGE;
        const uint32_t b_sm = a_sm + A_BYTES;

        #pragma unroll
        for (int ks = 0; ks < 4; ++ks) {
            uint32_t afrag[4][4], bfrag[3][4];
            #pragma unroll
            for (int mf = 0; mf < 4; ++mf)
                ldsm4(afrag[mf],
                      a_sm + SWZ((mf * 16 + a_row_off) * 128 + ks * 32 + a_k_off));
            #pragma unroll
            for (int nf2 = 0; nf2 < 3; ++nf2)
                ldsm4(bfrag[nf2],
                      b_sm + SWZ((warp_n + nf2 * 16 + b_n_off) * 128 + ks * 32 + b_k_off));
            #pragma unroll
            for (int mf = 0; mf < 4; ++mf)
                #pragma unroll
                for (int nf = 0; nf < 6; ++nf)
                    mma16816(acc[mf][nf], afrag[mf], &bfrag[nf >> 1][(nf & 1) * 2]);
        }
    }

    // ---- epilogue: GELU + float2 stores (no M guards: 12608 % 64 == 0)
    float* __restrict__ outbase =
        Out + (size_t)nb * (size_t)M_TOTAL * R_DIM + warp_n;
    const int rbase = bm + (lane >> 2);
    const int cbase = (lane & 3) * 2;
    #pragma unroll
    for (int mf = 0; mf < 4; ++mf) {
        #pragma unroll
        for (int half = 0; half < 2; ++half) {
            int row = rbase + mf * 16 + half * 8;
            float* op = outbase + (size_t)row * R_DIM + cbase;
            #pragma unroll
            for (int nf = 0; nf < 6; ++nf) {
                float2 o;
                o.x = gelu_exact(acc[mf][nf][half * 2 + 0]);
                o.y = gelu_exact(acc[mf][nf][half * 2 + 1]);
                *reinterpret_cast<float2*>(op + nf * 8) = o;
            }
        }
    }
}

extern "C" void kernel_launch(void* const* d_in, const int* in_sizes, int n_in,
                              void* d_out, int out_size) {
    const float* X  = (const float*)d_in[0];  // [64,197,768]
    const float* Wq = (const float*)d_in[1];  // [768,192]
    const float* Wk = (const float*)d_in[2];
    const float* Wv = (const float*)d_in[3];
    float* Out = (float*)d_out;

    cudaFuncSetAttribute(qkv_mma_kernel, cudaFuncAttributeMaxDynamicSharedMemorySize, SMEM_DYN);

    __half* xh_ptr = nullptr;
    cudaGetSymbolAddress((void**)&xh_ptr, g_Xh);

    cvt_xw_kernel<<<XBLK + WBLK, 256>>>((const float4*)X, Wq, Wk, Wv, (uint4*)xh_ptr);

    dim3 grid(3, M_TOTAL / BM);               // 3 x 197 = 591 CTAs = 1.996 waves @ 2/SM
    qkv_mma_kernel<<<grid, 128, SMEM_DYN>>>(Out);
}